// round 1
// baseline (speedup 1.0000x reference)
#include <cuda_runtime.h>

#define BATCH 4
#define SEQ   2048
#define HID   1024
#define NHEAD 16
#define HDIM  64

// Scratch (static device globals — allowed; no runtime allocation)
__device__ float g_q[BATCH*NHEAD*SEQ*HDIM];
__device__ float g_k[BATCH*NHEAD*SEQ*HDIM];
__device__ float g_v[BATCH*NHEAD*SEQ*HDIM];
__device__ float g_attn[BATCH*SEQ*HID];

// ---------------------------------------------------------------------------
// Stage 1: QKV GEMM  C[m][n] = x[m][:] . w_qkv[:][n] + b_qkv[n]
// M=8192, K=1024, N=3072. Epilogue scatters into head-major Q/K/V.
// 128x128 block tile, BK=8, 256 threads, 8x8 per-thread tile.
// ---------------------------------------------------------------------------
__global__ __launch_bounds__(256) void qkv_gemm(const float* __restrict__ A,
                                                const float* __restrict__ W,
                                                const float* __restrict__ bias)
{
    const int K = HID;
    const int N = 3 * HID;
    __shared__ float As[8][128];
    __shared__ float Bs[8][128];

    const int tid = threadIdx.x;
    const int m0 = blockIdx.y * 128;
    const int n0 = blockIdx.x * 128;

    const int arow = tid >> 1;          // 0..127
    const int acol = (tid & 1) * 4;     // 0 or 4
    const int brow = tid >> 5;          // 0..7
    const int bcol = (tid & 31) * 4;    // 0..124

    const float* Ap = A + (m0 + arow) * K + acol;
    const float* Bp = W + brow * N + n0 + bcol;

    float acc[8][8] = {};

    const int ty = tid >> 4, tx = tid & 15;

    for (int k0 = 0; k0 < K; k0 += 8) {
        float4 av = *(const float4*)(Ap + k0);
        float4 bv = *(const float4*)(Bp + (long)k0 * N);
        As[acol + 0][arow] = av.x;
        As[acol + 1][arow] = av.y;
        As[acol + 2][arow] = av.z;
        As[acol + 3][arow] = av.w;
        *(float4*)&Bs[brow][bcol] = bv;
        __syncthreads();

        #pragma unroll
        for (int kk = 0; kk < 8; kk++) {
            float4 a0 = *(const float4*)&As[kk][ty * 8];
            float4 a1 = *(const float4*)&As[kk][ty * 8 + 4];
            float4 b0 = *(const float4*)&Bs[kk][tx * 8];
            float4 b1 = *(const float4*)&Bs[kk][tx * 8 + 4];
            float a[8] = {a0.x,a0.y,a0.z,a0.w,a1.x,a1.y,a1.z,a1.w};
            float b[8] = {b0.x,b0.y,b0.z,b0.w,b1.x,b1.y,b1.z,b1.w};
            #pragma unroll
            for (int i = 0; i < 8; i++)
                #pragma unroll
                for (int j = 0; j < 8; j++)
                    acc[i][j] += a[i] * b[j];
        }
        __syncthreads();
    }

    // Epilogue: scatter to Q/K/V head-major layouts, add bias.
    #pragma unroll
    for (int i = 0; i < 8; i++) {
        const int m = m0 + ty * 8 + i;
        const int bb = m >> 11;          // / SEQ
        const int s  = m & 2047;
        #pragma unroll
        for (int j = 0; j < 8; j++) {
            const int n = n0 + tx * 8 + j;
            const float v = acc[i][j] + bias[n];
            const int which = n >> 10;
            const int rem = n & 1023;
            const int h = rem >> 6;
            const int d = rem & 63;
            const int idx = (((bb * NHEAD) + h) * SEQ + s) * HDIM + d;
            if (which == 0)      g_q[idx] = v;
            else if (which == 1) g_k[idx] = v;
            else                 g_v[idx] = v;
        }
    }
}

// ---------------------------------------------------------------------------
// Stage 2: causal flash attention, fp32.
// Block = 64 queries of one (b,h). 256 threads, 4x4 register tiles.
// K smem buffer reused for P. Dynamic smem 3*64*65 floats.
// ---------------------------------------------------------------------------
__global__ __launch_bounds__(256) void flash_attn()
{
    extern __shared__ float sm[];
    float (*Qs)[65]  = (float(*)[65])sm;
    float (*KPs)[65] = (float(*)[65])(sm + 64 * 65);
    float (*Vs)[65]  = (float(*)[65])(sm + 2 * 64 * 65);

    const int b  = blockIdx.z;
    const int h  = blockIdx.y;
    const int qt = blockIdx.x;
    const int q0 = qt * 64;

    const float* Qg  = g_q + (((long)(b * NHEAD + h)) * SEQ + q0) * HDIM;
    const float* Kg0 = g_k + ((long)(b * NHEAD + h)) * SEQ * HDIM;
    const float* Vg0 = g_v + ((long)(b * NHEAD + h)) * SEQ * HDIM;

    const int tid = threadIdx.x;
    const int ty = tid >> 4, tx = tid & 15;

    // load Q tile
    for (int i = tid; i < 64 * 64; i += 256) {
        Qs[i >> 6][i & 63] = Qg[i];
    }

    float m_i[4], l_i[4], acc[4][4];
    #pragma unroll
    for (int i = 0; i < 4; i++) {
        m_i[i] = -1e30f;
        l_i[i] = 0.0f;
        #pragma unroll
        for (int j = 0; j < 4; j++) acc[i][j] = 0.0f;
    }

    const float scale = 0.125f; // HD^-0.5
    const int ntiles = qt + 1;

    for (int t = 0; t < ntiles; t++) {
        const int k0 = t * 64;
        __syncthreads();   // prior PV reads done (and Q load at t=0)
        for (int i = tid; i < 64 * 64; i += 256) {
            const int r = i >> 6, c = i & 63;
            KPs[r][c] = Kg0[k0 * HDIM + i];
            Vs[r][c]  = Vg0[k0 * HDIM + i];
        }
        __syncthreads();

        // S = Q K^T   (4x4 per thread)
        float s[4][4] = {};
        #pragma unroll 4
        for (int d = 0; d < 64; d++) {
            float qv[4], kv[4];
            #pragma unroll
            for (int i = 0; i < 4; i++) qv[i] = Qs[4 * ty + i][d];
            #pragma unroll
            for (int j = 0; j < 4; j++) kv[j] = KPs[4 * tx + j][d];
            #pragma unroll
            for (int i = 0; i < 4; i++)
                #pragma unroll
                for (int j = 0; j < 4; j++)
                    s[i][j] += qv[i] * kv[j];
        }

        // scale + causal mask
        #pragma unroll
        for (int i = 0; i < 4; i++) {
            const int rg = q0 + 4 * ty + i;
            #pragma unroll
            for (int j = 0; j < 4; j++) {
                const int cg = k0 + 4 * tx + j;
                float val = s[i][j] * scale;
                if (cg > rg) val = -1e30f;
                s[i][j] = val;
            }
        }

        // online softmax (row reductions across 16-lane tx groups)
        #pragma unroll
        for (int i = 0; i < 4; i++) {
            float mx = fmaxf(fmaxf(s[i][0], s[i][1]), fmaxf(s[i][2], s[i][3]));
            #pragma unroll
            for (int off = 8; off >= 1; off >>= 1)
                mx = fmaxf(mx, __shfl_xor_sync(0xffffffffu, mx, off));
            const float mn = fmaxf(m_i[i], mx);
            const float corr = __expf(m_i[i] - mn);
            m_i[i] = mn;
            float rs = 0.0f;
            #pragma unroll
            for (int j = 0; j < 4; j++) {
                s[i][j] = __expf(s[i][j] - mn);
                rs += s[i][j];
            }
            #pragma unroll
            for (int off = 8; off >= 1; off >>= 1)
                rs += __shfl_xor_sync(0xffffffffu, rs, off);
            l_i[i] = l_i[i] * corr + rs;
            #pragma unroll
            for (int j = 0; j < 4; j++) acc[i][j] *= corr;
        }

        __syncthreads();   // everyone done reading K before overwriting as P
        #pragma unroll
        for (int i = 0; i < 4; i++)
            #pragma unroll
            for (int j = 0; j < 4; j++)
                KPs[4 * ty + i][4 * tx + j] = s[i][j];
        __syncthreads();

        // O += P V
        #pragma unroll 4
        for (int kk = 0; kk < 64; kk++) {
            float pv[4], vv[4];
            #pragma unroll
            for (int i = 0; i < 4; i++) pv[i] = KPs[4 * ty + i][kk];
            #pragma unroll
            for (int j = 0; j < 4; j++) vv[j] = Vs[kk][4 * tx + j];
            #pragma unroll
            for (int i = 0; i < 4; i++)
                #pragma unroll
                for (int j = 0; j < 4; j++)
                    acc[i][j] += pv[i] * vv[j];
        }
    }

    // write out: g_attn[b][s][h*HD + d]
    #pragma unroll
    for (int i = 0; i < 4; i++) {
        const int rg = q0 + 4 * ty + i;
        const float inv_l = 1.0f / l_i[i];
        #pragma unroll
        for (int j = 0; j < 4; j++) {
            g_attn[((long)(b * SEQ + rg)) * HID + h * HDIM + 4 * tx + j] =
                acc[i][j] * inv_l;
        }
    }
}

// ---------------------------------------------------------------------------
// Stage 3: output projection  out = attn @ w_out + b_out
// M=8192, K=1024, N=1024
// ---------------------------------------------------------------------------
__global__ __launch_bounds__(256) void out_gemm(const float* __restrict__ W,
                                                const float* __restrict__ bias,
                                                float* __restrict__ Out)
{
    const int K = HID;
    const int N = HID;
    __shared__ float As[8][128];
    __shared__ float Bs[8][128];

    const int tid = threadIdx.x;
    const int m0 = blockIdx.y * 128;
    const int n0 = blockIdx.x * 128;

    const int arow = tid >> 1;
    const int acol = (tid & 1) * 4;
    const int brow = tid >> 5;
    const int bcol = (tid & 31) * 4;

    const float* Ap = g_attn + (long)(m0 + arow) * K + acol;
    const float* Bp = W + brow * N + n0 + bcol;

    float acc[8][8] = {};
    const int ty = tid >> 4, tx = tid & 15;

    for (int k0 = 0; k0 < K; k0 += 8) {
        float4 av = *(const float4*)(Ap + k0);
        float4 bv = *(const float4*)(Bp + (long)k0 * N);
        As[acol + 0][arow] = av.x;
        As[acol + 1][arow] = av.y;
        As[acol + 2][arow] = av.z;
        As[acol + 3][arow] = av.w;
        *(float4*)&Bs[brow][bcol] = bv;
        __syncthreads();

        #pragma unroll
        for (int kk = 0; kk < 8; kk++) {
            float4 a0 = *(const float4*)&As[kk][ty * 8];
            float4 a1 = *(const float4*)&As[kk][ty * 8 + 4];
            float4 b0 = *(const float4*)&Bs[kk][tx * 8];
            float4 b1 = *(const float4*)&Bs[kk][tx * 8 + 4];
            float a[8] = {a0.x,a0.y,a0.z,a0.w,a1.x,a1.y,a1.z,a1.w};
            float b[8] = {b0.x,b0.y,b0.z,b0.w,b1.x,b1.y,b1.z,b1.w};
            #pragma unroll
            for (int i = 0; i < 8; i++)
                #pragma unroll
                for (int j = 0; j < 8; j++)
                    acc[i][j] += a[i] * b[j];
        }
        __syncthreads();
    }

    #pragma unroll
    for (int i = 0; i < 8; i++) {
        const int m = m0 + ty * 8 + i;
        #pragma unroll
        for (int j = 0; j < 8; j++) {
            const int n = n0 + tx * 8 + j;
            Out[(long)m * N + n] = acc[i][j] + bias[n];
        }
    }
}

// ---------------------------------------------------------------------------
extern "C" void kernel_launch(void* const* d_in, const int* in_sizes, int n_in,
                              void* d_out, int out_size)
{
    const float* x     = (const float*)d_in[0];
    const float* w_qkv = (const float*)d_in[1];
    const float* b_qkv = (const float*)d_in[2];
    const float* w_out = (const float*)d_in[3];
    const float* b_out = (const float*)d_in[4];
    float* out = (float*)d_out;

    // Stage 1: QKV projection + head scatter
    qkv_gemm<<<dim3(3 * HID / 128, (BATCH * SEQ) / 128), 256>>>(x, w_qkv, b_qkv);

    // Stage 2: causal flash attention
    const int shmem = 3 * 64 * 65 * (int)sizeof(float);  // 49920 B > 48KB default
    cudaFuncSetAttribute(flash_attn,
                         cudaFuncAttributeMaxDynamicSharedMemorySize, shmem);
    flash_attn<<<dim3(SEQ / 64, NHEAD, BATCH), 256, shmem>>>();

    // Stage 3: output projection
    out_gemm<<<dim3(HID / 128, (BATCH * SEQ) / 128), 256>>>(w_out, b_out, out);
}

// round 8
// speedup vs baseline: 1.0542x; 1.0542x over previous
#include <cuda_runtime.h>

#define BATCH 4
#define SEQ   2048
#define HID   1024
#define NHEAD 16
#define HDIM  64

// Scratch (static device globals — allowed; no runtime allocation)
__device__ float g_q[BATCH*NHEAD*SEQ*HDIM];
__device__ float g_k[BATCH*NHEAD*SEQ*HDIM];
__device__ float g_v[BATCH*NHEAD*SEQ*HDIM];
__device__ float g_attn[BATCH*SEQ*HID];

// ---------------------------------------------------------------------------
// Stage 1: QKV GEMM  C[m][n] = x[m][:] . w_qkv[:][n] + b_qkv[n]
// M=8192, K=1024, N=3072. Epilogue scatters into head-major Q/K/V.
// 128x128 block tile, BK=8, 256 threads, 8x8 per-thread tile.
// Identical to R1 except: next tile's LDGs are issued BEFORE compute
// (register staging), hiding global latency under the FMA block.
// ---------------------------------------------------------------------------
__global__ __launch_bounds__(256) void qkv_gemm(const float* __restrict__ A,
                                                const float* __restrict__ W,
                                                const float* __restrict__ bias)
{
    const int K = HID;
    const int N = 3 * HID;
    __shared__ float As[8][128];
    __shared__ float Bs[8][128];

    const int tid = threadIdx.x;
    const int m0 = blockIdx.y * 128;
    const int n0 = blockIdx.x * 128;

    const int arow = tid >> 1;          // 0..127
    const int acol = (tid & 1) * 4;     // 0 or 4
    const int brow = tid >> 5;          // 0..7
    const int bcol = (tid & 31) * 4;    // 0..124

    const float* Ap = A + (m0 + arow) * K + acol;
    const float* Bp = W + brow * N + n0 + bcol;

    float acc[8][8] = {};
    const int ty = tid >> 4, tx = tid & 15;

    // stage tile 0
    float4 av = *(const float4*)(Ap);
    float4 bv = *(const float4*)(Bp);

    for (int k0 = 0; k0 < K; k0 += 8) {
        // store staged registers to smem
        As[acol + 0][arow] = av.x;
        As[acol + 1][arow] = av.y;
        As[acol + 2][arow] = av.z;
        As[acol + 3][arow] = av.w;
        *(float4*)&Bs[brow][bcol] = bv;
        __syncthreads();

        // issue next tile's loads now; latency overlaps the compute below
        if (k0 + 8 < K) {
            av = *(const float4*)(Ap + k0 + 8);
            bv = *(const float4*)(Bp + (long)(k0 + 8) * N);
        }

        #pragma unroll
        for (int kk = 0; kk < 8; kk++) {
            float4 a0 = *(const float4*)&As[kk][ty * 8];
            float4 a1 = *(const float4*)&As[kk][ty * 8 + 4];
            float4 b0 = *(const float4*)&Bs[kk][tx * 8];
            float4 b1 = *(const float4*)&Bs[kk][tx * 8 + 4];
            float a[8] = {a0.x,a0.y,a0.z,a0.w,a1.x,a1.y,a1.z,a1.w};
            float b[8] = {b0.x,b0.y,b0.z,b0.w,b1.x,b1.y,b1.z,b1.w};
            #pragma unroll
            for (int i = 0; i < 8; i++)
                #pragma unroll
                for (int j = 0; j < 8; j++)
                    acc[i][j] += a[i] * b[j];
        }
        __syncthreads();
    }

    // Epilogue: scatter to Q/K/V head-major layouts, add bias.
    #pragma unroll
    for (int i = 0; i < 8; i++) {
        const int m = m0 + ty * 8 + i;
        const int bb = m >> 11;          // / SEQ
        const int s  = m & 2047;
        #pragma unroll
        for (int j = 0; j < 8; j++) {
            const int n = n0 + tx * 8 + j;
            const float v = acc[i][j] + bias[n];
            const int which = n >> 10;
            const int rem = n & 1023;
            const int h = rem >> 6;
            const int d = rem & 63;
            const int idx = (((bb * NHEAD) + h) * SEQ + s) * HDIM + d;
            if (which == 0)      g_q[idx] = v;
            else if (which == 1) g_k[idx] = v;
            else                 g_v[idx] = v;
        }
    }
}

// ---------------------------------------------------------------------------
// Stage 2: causal flash attention, fp32.
// Byte-identical to the R1 passing version.
// ---------------------------------------------------------------------------
__global__ __launch_bounds__(256) void flash_attn()
{
    extern __shared__ float sm[];
    float (*Qs)[65]  = (float(*)[65])sm;
    float (*KPs)[65] = (float(*)[65])(sm + 64 * 65);
    float (*Vs)[65]  = (float(*)[65])(sm + 2 * 64 * 65);

    const int b  = blockIdx.z;
    const int h  = blockIdx.y;
    const int qt = blockIdx.x;
    const int q0 = qt * 64;

    const float* Qg  = g_q + (((long)(b * NHEAD + h)) * SEQ + q0) * HDIM;
    const float* Kg0 = g_k + ((long)(b * NHEAD + h)) * SEQ * HDIM;
    const float* Vg0 = g_v + ((long)(b * NHEAD + h)) * SEQ * HDIM;

    const int tid = threadIdx.x;
    const int ty = tid >> 4, tx = tid & 15;

    // load Q tile
    for (int i = tid; i < 64 * 64; i += 256) {
        Qs[i >> 6][i & 63] = Qg[i];
    }

    float m_i[4], l_i[4], acc[4][4];
    #pragma unroll
    for (int i = 0; i < 4; i++) {
        m_i[i] = -1e30f;
        l_i[i] = 0.0f;
        #pragma unroll
        for (int j = 0; j < 4; j++) acc[i][j] = 0.0f;
    }

    const float scale = 0.125f; // HD^-0.5
    const int ntiles = qt + 1;

    for (int t = 0; t < ntiles; t++) {
        const int k0 = t * 64;
        __syncthreads();   // prior PV reads done (and Q load at t=0)
        for (int i = tid; i < 64 * 64; i += 256) {
            const int r = i >> 6, c = i & 63;
            KPs[r][c] = Kg0[k0 * HDIM + i];
            Vs[r][c]  = Vg0[k0 * HDIM + i];
        }
        __syncthreads();

        // S = Q K^T   (4x4 per thread)
        float s[4][4] = {};
        #pragma unroll 4
        for (int d = 0; d < 64; d++) {
            float qv[4], kv[4];
            #pragma unroll
            for (int i = 0; i < 4; i++) qv[i] = Qs[4 * ty + i][d];
            #pragma unroll
            for (int j = 0; j < 4; j++) kv[j] = KPs[4 * tx + j][d];
            #pragma unroll
            for (int i = 0; i < 4; i++)
                #pragma unroll
                for (int j = 0; j < 4; j++)
                    s[i][j] += qv[i] * kv[j];
        }

        // scale + causal mask
        #pragma unroll
        for (int i = 0; i < 4; i++) {
            const int rg = q0 + 4 * ty + i;
            #pragma unroll
            for (int j = 0; j < 4; j++) {
                const int cg = k0 + 4 * tx + j;
                float val = s[i][j] * scale;
                if (cg > rg) val = -1e30f;
                s[i][j] = val;
            }
        }

        // online softmax (row reductions across 16-lane tx groups)
        #pragma unroll
        for (int i = 0; i < 4; i++) {
            float mx = fmaxf(fmaxf(s[i][0], s[i][1]), fmaxf(s[i][2], s[i][3]));
            #pragma unroll
            for (int off = 8; off >= 1; off >>= 1)
                mx = fmaxf(mx, __shfl_xor_sync(0xffffffffu, mx, off));
            const float mn = fmaxf(m_i[i], mx);
            const float corr = __expf(m_i[i] - mn);
            m_i[i] = mn;
            float rs = 0.0f;
            #pragma unroll
            for (int j = 0; j < 4; j++) {
                s[i][j] = __expf(s[i][j] - mn);
                rs += s[i][j];
            }
            #pragma unroll
            for (int off = 8; off >= 1; off >>= 1)
                rs += __shfl_xor_sync(0xffffffffu, rs, off);
            l_i[i] = l_i[i] * corr + rs;
            #pragma unroll
            for (int j = 0; j < 4; j++) acc[i][j] *= corr;
        }

        __syncthreads();   // everyone done reading K before overwriting as P
        #pragma unroll
        for (int i = 0; i < 4; i++)
            #pragma unroll
            for (int j = 0; j < 4; j++)
                KPs[4 * ty + i][4 * tx + j] = s[i][j];
        __syncthreads();

        // O += P V
        #pragma unroll 4
        for (int kk = 0; kk < 64; kk++) {
            float pv[4], vv[4];
            #pragma unroll
            for (int i = 0; i < 4; i++) pv[i] = KPs[4 * ty + i][kk];
            #pragma unroll
            for (int j = 0; j < 4; j++) vv[j] = Vs[kk][4 * tx + j];
            #pragma unroll
            for (int i = 0; i < 4; i++)
                #pragma unroll
                for (int j = 0; j < 4; j++)
                    acc[i][j] += pv[i] * vv[j];
        }
    }

    // write out: g_attn[b][s][h*HD + d]
    #pragma unroll
    for (int i = 0; i < 4; i++) {
        const int rg = q0 + 4 * ty + i;
        const float inv_l = 1.0f / l_i[i];
        #pragma unroll
        for (int j = 0; j < 4; j++) {
            g_attn[((long)(b * SEQ + rg)) * HID + h * HDIM + 4 * tx + j] =
                acc[i][j] * inv_l;
        }
    }
}

// ---------------------------------------------------------------------------
// Stage 3: output projection  out = attn @ w_out + b_out
// M=8192, K=1024, N=1024. Same register-staged load placement as qkv_gemm.
// ---------------------------------------------------------------------------
__global__ __launch_bounds__(256) void out_gemm(const float* __restrict__ W,
                                                const float* __restrict__ bias,
                                                float* __restrict__ Out)
{
    const int K = HID;
    const int N = HID;
    __shared__ float As[8][128];
    __shared__ float Bs[8][128];

    const int tid = threadIdx.x;
    const int m0 = blockIdx.y * 128;
    const int n0 = blockIdx.x * 128;

    const int arow = tid >> 1;
    const int acol = (tid & 1) * 4;
    const int brow = tid >> 5;
    const int bcol = (tid & 31) * 4;

    const float* Ap = g_attn + (long)(m0 + arow) * K + acol;
    const float* Bp = W + brow * N + n0 + bcol;

    float acc[8][8] = {};
    const int ty = tid >> 4, tx = tid & 15;

    float4 av = *(const float4*)(Ap);
    float4 bv = *(const float4*)(Bp);

    for (int k0 = 0; k0 < K; k0 += 8) {
        As[acol + 0][arow] = av.x;
        As[acol + 1][arow] = av.y;
        As[acol + 2][arow] = av.z;
        As[acol + 3][arow] = av.w;
        *(float4*)&Bs[brow][bcol] = bv;
        __syncthreads();

        if (k0 + 8 < K) {
            av = *(const float4*)(Ap + k0 + 8);
            bv = *(const float4*)(Bp + (long)(k0 + 8) * N);
        }

        #pragma unroll
        for (int kk = 0; kk < 8; kk++) {
            float4 a0 = *(const float4*)&As[kk][ty * 8];
            float4 a1 = *(const float4*)&As[kk][ty * 8 + 4];
            float4 b0 = *(const float4*)&Bs[kk][tx * 8];
            float4 b1 = *(const float4*)&Bs[kk][tx * 8 + 4];
            float a[8] = {a0.x,a0.y,a0.z,a0.w,a1.x,a1.y,a1.z,a1.w};
            float b[8] = {b0.x,b0.y,b0.z,b0.w,b1.x,b1.y,b1.z,b1.w};
            #pragma unroll
            for (int i = 0; i < 8; i++)
                #pragma unroll
                for (int j = 0; j < 8; j++)
                    acc[i][j] += a[i] * b[j];
        }
        __syncthreads();
    }

    #pragma unroll
    for (int i = 0; i < 8; i++) {
        const int m = m0 + ty * 8 + i;
        #pragma unroll
        for (int j = 0; j < 8; j++) {
            const int n = n0 + tx * 8 + j;
            Out[(long)m * N + n] = acc[i][j] + bias[n];
        }
    }
}

// ---------------------------------------------------------------------------
extern "C" void kernel_launch(void* const* d_in, const int* in_sizes, int n_in,
                              void* d_out, int out_size)
{
    const float* x     = (const float*)d_in[0];
    const float* w_qkv = (const float*)d_in[1];
    const float* b_qkv = (const float*)d_in[2];
    const float* w_out = (const float*)d_in[3];
    const float* b_out = (const float*)d_in[4];
    float* out = (float*)d_out;

    // Stage 1: QKV projection + head scatter
    qkv_gemm<<<dim3(3 * HID / 128, (BATCH * SEQ) / 128), 256>>>(x, w_qkv, b_qkv);

    // Stage 2: causal flash attention
    const int shmem = 3 * 64 * 65 * (int)sizeof(float);  // 49920 B > 48KB default
    cudaFuncSetAttribute(flash_attn,
                         cudaFuncAttributeMaxDynamicSharedMemorySize, shmem);
    flash_attn<<<dim3(SEQ / 64, NHEAD, BATCH), 256, shmem>>>();

    // Stage 3: output projection
    out_gemm<<<dim3(HID / 128, (BATCH * SEQ) / 128), 256>>>(w_out, b_out, out);
}